// round 16
// baseline (speedup 1.0000x reference)
#include <cuda_runtime.h>
#include <cuda_fp16.h>
#include <math.h>
#include <stdint.h>

#define T_CTX 100000
#define H 256

// ---- GEMM tiling (round-8 proven: warp tile 32x64, CTA 64x256, 2 CTA/SM) ----
#define TILE_M 64
#define NB_G ((T_CTX + TILE_M - 1) / TILE_M)     // 1563
#define KT 64
#define NCH (H / KT)                             // 4
#define ASTR 72
#define ABUF_H (TILE_M * ASTR)
#define BBUF_H (H * ASTR)
#define SMEM_GEMM ((4 * ABUF_H + 2 * BBUF_H) * 2 + (4 * TILE_M + TILE_M) * 4) // 111872

// ---- tail ----
#define AL4_BLOCKS 25                            // alphat float4 blocks (25*1024*4 >= T)
#define CTR1_BLOCKS 32
#define CTR_ROWS (CTR1_BLOCKS * 16)              // 512 partial rows
#define CTR2_BLOCKS 8

// Scratch (static device globals: allocation-free per harness rules)
__device__ float g_At[T_CTX];
__device__ float g_proj[H];
__device__ __half g_WmTh[H * H];                 // Wm transposed, fp16(rn)
__device__ float g_lse;
__device__ float g_sm_m[NB_G];
__device__ float g_sm_s[NB_G];
__device__ float g_ct1[NB_G][H];
__device__ float g_cs1[NB_G][H];
__device__ float g_ct2[CTR_ROWS][H];
__device__ float g_cs2[CTR_ROWS][H];

// ===========================================================================
// helpers
// ===========================================================================
__device__ __forceinline__ float tanh_fast(float x) {
    float y;
    asm("tanh.approx.f32 %0, %1;" : "=f"(y) : "f"(x));
    return y;
}
__device__ __forceinline__ uint32_t smem_u32(const void* p) {
    uint32_t a;
    asm("{ .reg .u64 t; cvta.to.shared.u64 t, %1; cvt.u32.u64 %0, t; }" : "=r"(a) : "l"(p));
    return a;
}
__device__ __forceinline__ void cp16(uint32_t dst, const void* src) {
    asm volatile("cp.async.cg.shared.global [%0], [%1], 16;" :: "r"(dst), "l"(src) : "memory");
}
__device__ __forceinline__ void cp_commit() {
    asm volatile("cp.async.commit_group;" ::: "memory");
}
__device__ __forceinline__ void ldsm4(uint32_t& r0, uint32_t& r1, uint32_t& r2, uint32_t& r3,
                                      uint32_t addr) {
    asm volatile("ldmatrix.sync.aligned.m8n8.x4.shared.b16 {%0,%1,%2,%3}, [%4];"
                 : "=r"(r0), "=r"(r1), "=r"(r2), "=r"(r3) : "r"(addr));
}
__device__ __forceinline__ void mma_f16(float d[4], const uint32_t a[4], const uint32_t b[2]) {
    asm volatile(
        "mma.sync.aligned.m16n8k16.row.col.f32.f16.f16.f32 "
        "{%0,%1,%2,%3}, {%4,%5,%6,%7}, {%8,%9}, {%0,%1,%2,%3};"
        : "+f"(d[0]), "+f"(d[1]), "+f"(d[2]), "+f"(d[3])
        : "r"(a[0]), "r"(a[1]), "r"(a[2]), "r"(a[3]), "r"(b[0]), "r"(b[1]));
}

// ===========================================================================
// prep: blocks 0..63 transpose Wm -> fp16 WmTh;
//       blocks 64..95 proj (warp-per-row, coalesced, butterfly reduce)
// ===========================================================================
__global__ void prep_kernel(const float* __restrict__ Wm,
                            const float* __restrict__ hc,
                            const float* __restrict__ W1) {
    if (blockIdx.x >= 64) {
        const int lane = threadIdx.x;
        const int row = (blockIdx.x - 64) * 8 + threadIdx.y;
        float s = 0.f;
#pragma unroll
        for (int i = 0; i < 8; ++i) {
            int k = lane + i * 32;
            s = fmaf(hc[k], W1[row * H + k], s);
        }
#pragma unroll
        for (int off = 16; off > 0; off >>= 1)
            s += __shfl_xor_sync(~0u, s, off);
        if (lane == 0) g_proj[row] = s;
        return;
    }
    __shared__ float t[32][33];
    int bx = blockIdx.x & 7, by = blockIdx.x >> 3;
    int x = bx * 32 + threadIdx.x;
#pragma unroll
    for (int j = 0; j < 4; ++j) {
        int y = by * 32 + threadIdx.y + j * 8;
        t[threadIdx.y + j * 8][threadIdx.x] = Wm[y * H + x];
    }
    __syncthreads();
    int x2 = by * 32 + threadIdx.x;
#pragma unroll
    for (int j = 0; j < 4; ++j) {
        int y2 = bx * 32 + threadIdx.y + j * 8;
        g_WmTh[y2 * H + x2] = __float2half_rn(t[threadIdx.x][threadIdx.y + j * 8]);
    }
}

// ===========================================================================
// Fused GEMM + tanh + V-dot + ct partials + per-CTA softmax partials.
// (round-13 proven, UNCHANGED)
// ===========================================================================
__global__ void __launch_bounds__(256, 2)
gemm_tanh_mma(const float* __restrict__ A, const float* __restrict__ V) {
    extern __shared__ __half smh[];
    __half* As = smh;                            // [4][TILE_M][ASTR]
    __half* Bs = smh + 4 * ABUF_H;               // [2][H][ASTR]
    float* red = (float*)(smh + 4 * ABUF_H + 2 * BBUF_H);
    float* at_s = red + 4 * TILE_M;
    const uint32_t as_u = smem_u32(As);
    const uint32_t bs_u = smem_u32(Bs);

    const int tid = threadIdx.x;
    const int wid = tid >> 5;
    const int lane = tid & 31;
    const int g = lane >> 2;
    const int t = lane & 3;
    const int rg = wid >> 2;
    const int wc = wid & 3;
    const int row0 = blockIdx.x * TILE_M;

    uint32_t a_lm[2], b_lm[4];
#pragma unroll
    for (int mt = 0; mt < 2; ++mt)
        a_lm[mt] = as_u + 2u * ((uint32_t)(rg * 32 + mt * 16 + (lane & 7) +
                                ((lane >> 3) & 1) * 8) * ASTR + ((lane >> 4) & 1) * 8);
#pragma unroll
    for (int np = 0; np < 4; ++np)
        b_lm[np] = bs_u + 2u * ((uint32_t)(wc * 64 + np * 16 + (lane & 7) +
                                ((lane >> 4) & 1) * 8) * ASTR + ((lane >> 3) & 1) * 8);

    float4 pa[4];
    float acc[2][8][4];
#pragma unroll
    for (int mt = 0; mt < 2; ++mt)
#pragma unroll
        for (int nt = 0; nt < 8; ++nt)
#pragma unroll
            for (int r = 0; r < 4; ++r) acc[mt][nt][r] = 0.f;

    auto ldgA = [&](int ch) {
        const int k0 = ch * KT;
#pragma unroll
        for (int i = 0; i < 4; ++i) {
            int idx = tid + i * 256;
            int r = idx >> 4;
            int c = (idx & 15) * 4;
            int grow = row0 + r;
            pa[i] = (grow < T_CTX)
                ? *reinterpret_cast<const float4*>(&A[(size_t)grow * H + k0 + c])
                : make_float4(0.f, 0.f, 0.f, 0.f);
        }
    };
    auto stsA = [&](int buf) {
#pragma unroll
        for (int i = 0; i < 4; ++i) {
            int idx = tid + i * 256;
            int r = idx >> 4;
            int c = (idx & 15) * 4;
            *reinterpret_cast<__half2*>(&As[buf * ABUF_H + r * ASTR + c]) =
                __floats2half2_rn(pa[i].x, pa[i].y);
            *reinterpret_cast<__half2*>(&As[buf * ABUF_H + r * ASTR + c + 2]) =
                __floats2half2_rn(pa[i].z, pa[i].w);
        }
    };
    auto cpB = [&](int ch, int buf) {
        const int k0 = ch * KT;
#pragma unroll
        for (int i = 0; i < 8; ++i) {
            int idx = tid + i * 256;
            int n = idx >> 3;
            int c8 = (idx & 7) * 8;
            cp16(bs_u + (uint32_t)(buf * BBUF_H + n * ASTR + c8) * 2,
                 g_WmTh + (size_t)n * H + k0 + c8);
        }
        cp_commit();
    };

    auto compute = [&](int ch, int bbuf) {
        const uint32_t aoff = (uint32_t)ch * (ABUF_H * 2);
        const uint32_t boff = (uint32_t)bbuf * (BBUF_H * 2);
#pragma unroll
        for (int ks = 0; ks < 4; ++ks) {
            const uint32_t koff = ks * 32;
            uint32_t bf[8][2];
#pragma unroll
            for (int np = 0; np < 4; ++np)
                ldsm4(bf[2 * np][0], bf[2 * np][1], bf[2 * np + 1][0], bf[2 * np + 1][1],
                      b_lm[np] + boff + koff);
#pragma unroll
            for (int mt = 0; mt < 2; ++mt) {
                uint32_t af[4];
                ldsm4(af[0], af[1], af[2], af[3], a_lm[mt] + aoff + koff);
#pragma unroll
                for (int nt = 0; nt < 8; ++nt)
                    mma_f16(acc[mt][nt], af, bf[nt]);
            }
        }
    };

    // prologue
    ldgA(0); cpB(0, 0);
    stsA(0);
    ldgA(1); cpB(1, 1);
    asm volatile("cp.async.wait_group 1;" ::: "memory");
    __syncthreads();

    // mainloop
#pragma unroll
    for (int ch = 0; ch < NCH; ++ch) {
        const int bbuf = ch & 1;
        if (ch < NCH - 1) stsA(ch + 1);
        if (ch < NCH - 2) ldgA(ch + 2);
        compute(ch, bbuf);
        if (ch < NCH - 1) {
            __syncthreads();
            if (ch < NCH - 2) {
                cpB(ch + 2, bbuf);
                asm volatile("cp.async.wait_group 1;" ::: "memory");
            } else {
                asm volatile("cp.async.wait_group 0;" ::: "memory");
            }
            __syncthreads();
        }
    }

    // epilogue 1: tanh + V-dot
    float p[4] = {0.f, 0.f, 0.f, 0.f};
#pragma unroll
    for (int nt = 0; nt < 8; ++nt) {
        int cn = wc * 64 + nt * 8 + t * 2;
        float v0 = V[cn],      v1 = V[cn + 1];
        float q0 = g_proj[cn], q1 = g_proj[cn + 1];
#pragma unroll
        for (int mt = 0; mt < 2; ++mt) {
            p[mt * 2 + 0] = fmaf(tanh_fast(acc[mt][nt][0] + q0), v0,
                            fmaf(tanh_fast(acc[mt][nt][1] + q1), v1, p[mt * 2 + 0]));
            p[mt * 2 + 1] = fmaf(tanh_fast(acc[mt][nt][2] + q0), v0,
                            fmaf(tanh_fast(acc[mt][nt][3] + q1), v1, p[mt * 2 + 1]));
        }
    }
#pragma unroll
    for (int j = 0; j < 4; ++j) {
        p[j] += __shfl_xor_sync(0xffffffffu, p[j], 1);
        p[j] += __shfl_xor_sync(0xffffffffu, p[j], 2);
    }
    if (t == 0) {
#pragma unroll
        for (int mt = 0; mt < 2; ++mt)
#pragma unroll
            for (int h = 0; h < 2; ++h)
                red[wc * TILE_M + rg * 32 + mt * 16 + h * 8 + g] = p[mt * 2 + h];
    }
    __syncthreads();
    if (tid < TILE_M) {
        float s = ((red[tid] + red[TILE_M + tid]) +
                   (red[2 * TILE_M + tid] + red[3 * TILE_M + tid]));
        at_s[tid] = s;
        int grow = row0 + tid;
        if (grow < T_CTX) g_At[grow] = s;
    }
    __syncthreads();

    // epilogue 1b: per-CTA softmax partial (warp 0)
    if (wid == 0) {
        float v0 = (row0 + lane      < T_CTX) ? at_s[lane]      : -1e30f;
        float v1 = (row0 + 32 + lane < T_CTX) ? at_s[lane + 32] : -1e30f;
        float m = fmaxf(v0, v1);
#pragma unroll
        for (int s = 16; s > 0; s >>= 1) m = fmaxf(m, __shfl_xor_sync(~0u, m, s));
        float sum = expf(v0 - m) + expf(v1 - m);
#pragma unroll
        for (int s = 16; s > 0; s >>= 1) sum += __shfl_xor_sync(~0u, sum, s);
        if (lane == 0) { g_sm_m[blockIdx.x] = m; g_sm_s[blockIdx.x] = sum; }
    }

    // epilogue 2: ct partials from resident fp16 A tiles
    {
        const int c = tid;
        const __half* col = As + (c >> 6) * ABUF_H + (c & 63);
        float s1 = 0.f, s2 = 0.f;
#pragma unroll 8
        for (int r = 0; r < TILE_M; ++r) {
            float f = __half2float(col[r * ASTR]);
            s1 = fmaf(at_s[r], f, s1);
            s2 += f;
        }
        g_ct1[blockIdx.x][c] = s1;
        g_cs1[blockIdx.x][c] = s2;
    }
}

// ===========================================================================
// post1: block 0 merges 1563 (m,S) pairs -> g_lse;
//        blocks 1..32 = ct reduction stage 1 (512 partial rows).
// ===========================================================================
__global__ void __launch_bounds__(1024)
post1_kernel() {
    const int tid = threadIdx.x;
    if (blockIdx.x == 0) {
        __shared__ float wred[32];
        const int lane = tid & 31;
        const int wid = tid >> 5;

        float m = -1e30f;
        for (int i = tid; i < NB_G; i += 1024) m = fmaxf(m, g_sm_m[i]);
#pragma unroll
        for (int s = 16; s > 0; s >>= 1) m = fmaxf(m, __shfl_xor_sync(~0u, m, s));
        if (lane == 0) wred[wid] = m;
        __syncthreads();
        if (wid == 0) {
            float mm = wred[lane];
#pragma unroll
            for (int s = 16; s > 0; s >>= 1) mm = fmaxf(mm, __shfl_xor_sync(~0u, mm, s));
            wred[lane] = mm;
        }
        __syncthreads();
        const float M = wred[0];
        __syncthreads();

        float S = 0.f;
        for (int i = tid; i < NB_G; i += 1024) S += g_sm_s[i] * expf(g_sm_m[i] - M);
#pragma unroll
        for (int s = 16; s > 0; s >>= 1) S += __shfl_xor_sync(~0u, S, s);
        if (lane == 0) wred[wid] = S;
        __syncthreads();
        if (tid == 0) {
            float SS = 0.f;
#pragma unroll
            for (int i = 0; i < 32; ++i) SS += wred[i];   // fixed order
            g_lse = M + logf(SS);
        }
    } else {
        const int j = blockIdx.x - 1;
        const int rl = tid >> 6;
        const int fc = (tid & 63) * 4;
        const int row = j * 16 + rl;             // 0..511

        float4 s1 = make_float4(0.f, 0.f, 0.f, 0.f);
        float4 s2 = make_float4(0.f, 0.f, 0.f, 0.f);
        for (int b = row; b < NB_G; b += CTR_ROWS) {
            float4 v1 = *reinterpret_cast<const float4*>(&g_ct1[b][fc]);
            float4 v2 = *reinterpret_cast<const float4*>(&g_cs1[b][fc]);
            s1.x += v1.x; s1.y += v1.y; s1.z += v1.z; s1.w += v1.w;
            s2.x += v2.x; s2.y += v2.y; s2.z += v2.z; s2.w += v2.w;
        }
        *reinterpret_cast<float4*>(&g_ct2[row][fc]) = s1;
        *reinterpret_cast<float4*>(&g_cs2[row][fc]) = s2;
    }
}

// ===========================================================================
// post2: lse ready scalar. blocks 0..24 = alphat (float4); 25..32 = ct stage 2.
// T_CTX = 100000 = 25000 float4 exactly; 25 blocks x 1000 active threads.
// ===========================================================================
__global__ void __launch_bounds__(1024)
post2_kernel(float* __restrict__ out) {
    const int tid = threadIdx.x;
    const float lse = g_lse;

    if (blockIdx.x < AL4_BLOCKS) {
        int e4 = blockIdx.x * 1024 + tid;        // float4 index
        if (e4 < T_CTX / 4) {
            float4 v = *reinterpret_cast<const float4*>(&g_At[e4 * 4]);
            v.x -= lse; v.y -= lse; v.z -= lse; v.w -= lse;
            *reinterpret_cast<float4*>(&out[e4 * 4]) = v;
        }
    } else {
        __shared__ float sm1[32][32];
        __shared__ float sm2[32][32];
        const int j2 = blockIdx.x - AL4_BLOCKS;  // 0..7
        const int cl = tid & 31;
        const int rs = tid >> 5;                 // 0..31
        const int c = j2 * 32 + cl;

        float s1 = 0.f, s2 = 0.f;
        const int r0 = rs * (CTR_ROWS / 32);     // 16 rows per slice
#pragma unroll 4
        for (int r = r0; r < r0 + CTR_ROWS / 32; ++r) {    // fixed order
            s1 += g_ct2[r][c];
            s2 += g_cs2[r][c];
        }
        sm1[rs][cl] = s1;
        sm2[rs][cl] = s2;
        __syncthreads();
        if (rs == 0) {
            float t1 = 0.f, t2 = 0.f;
#pragma unroll
            for (int i = 0; i < 32; ++i) {       // fixed order
                t1 += sm1[i][cl];
                t2 += sm2[i][cl];
            }
            out[T_CTX + c] = t1 - lse * t2;
        }
    }
}

// ===========================================================================
extern "C" void kernel_launch(void* const* d_in, const int* in_sizes, int n_in,
                              void* d_out, int out_size) {
    const float* inputs = (const float*)d_in[0];   // (T, H)
    const float* hc     = (const float*)d_in[1];   // (1, H)
    const float* Wm     = (const float*)d_in[2];   // (H, H)
    const float* V      = (const float*)d_in[3];   // (H, 1)
    const float* W1     = (const float*)d_in[4];   // (H, H)
    float* out = (float*)d_out;                    // [alphat (T) | ct (H)]

    static int smem_set = 0;
    if (!smem_set) {
        cudaFuncSetAttribute(gemm_tanh_mma,
                             cudaFuncAttributeMaxDynamicSharedMemorySize, SMEM_GEMM);
        smem_set = 1;
    }

    prep_kernel<<<96, dim3(32, 8)>>>(Wm, hc, W1);
    gemm_tanh_mma<<<NB_G, 256, SMEM_GEMM>>>(inputs, V);
    post1_kernel<<<1 + CTR1_BLOCKS, 1024>>>();
    post2_kernel<<<AL4_BLOCKS + CTR2_BLOCKS, 1024>>>(out);
}